// round 2
// baseline (speedup 1.0000x reference)
#include <cuda_runtime.h>
#include <cuda_bf16.h>
#include <math.h>

// Problem constants
#define Bb 8
#define Tt 2048
#define Dd 768
#define VQ 64
#define L2b 12
#define HID 1024
#define KK 4096
#define NMID 4
#define BT (Bb*Tt)          // 16384
#define EPS_N 1e-6f
#define EPS_BN 1e-5f

// ---------------- device scratch (no allocs allowed) ----------------
__device__ float g_z0[KK*HID];
__device__ float g_z1[KK*HID];
__device__ float g_scale[HID];
__device__ float g_shift[HID];
__device__ float g_embed[KK*VQ];
__device__ float g_ck[KK];          // 0.5 * ||e_k||^2
__device__ float g_hn[BT*VQ];
__device__ int   g_code[BT];

// ---------------- layer 0: bits @ W_in^T + b_in -> g_z0 ----------------
__global__ void k_layer0(const float* __restrict__ w_in, const float* __restrict__ b_in) {
    int idx = blockIdx.x * blockDim.x + threadIdx.x;     // KK*HID threads
    int k = idx >> 10;
    int h = idx & 1023;
    const float* w = w_in + h * L2b;
    float s = b_in[h];
#pragma unroll
    for (int j = 0; j < L2b; j++) {
        if ((k >> (11 - j)) & 1) s += w[j];
    }
    g_z0[idx] = s;
}

// ---------------- BN stats over K=4096 rows, per column ----------------
// which==0 reads g_z0, which==1 reads g_z1
__global__ void k_bnstats(int which, const float* __restrict__ gamma, const float* __restrict__ beta) {
    const float* Z = which ? g_z1 : g_z0;
    int h = blockIdx.x;
    int t = threadIdx.x;  // 256
    double s = 0.0, s2 = 0.0;
    for (int k = t; k < KK; k += 256) {
        float v = Z[k * HID + h];
        s += (double)v;
        s2 += (double)v * (double)v;
    }
    __shared__ double ss[256], ss2[256];
    ss[t] = s; ss2[t] = s2;
    __syncthreads();
    for (int o = 128; o > 0; o >>= 1) {
        if (t < o) { ss[t] += ss[t + o]; ss2[t] += ss2[t + o]; }
        __syncthreads();
    }
    if (t == 0) {
        double m = ss[0] / (double)KK;
        double var = ss2[0] / (double)KK - m * m;
        if (var < 0.0) var = 0.0;
        float rstd = (float)(1.0 / sqrt(var + (double)EPS_BN));
        float sc = gamma[h] * rstd;
        g_scale[h] = sc;
        g_shift[h] = beta[h] - (float)m * sc;
    }
}

// ---------------- mid GEMM: C = relu(bn(A)) @ W^T + bias ----------------
// A [4096,1024], W [1024,1024] row-major (out,in). 128x128x8 tile, 8x8 microtile.
// src==0: A=g_z0, C=g_z1 ; src==1: A=g_z1, C=g_z0
__global__ __launch_bounds__(256) void k_gemm(int src, const float* __restrict__ W,
                                              const float* __restrict__ bias) {
    const float* A = src ? g_z1 : g_z0;
    float* C       = src ? g_z0 : g_z1;
    __shared__ float As[8][128];
    __shared__ float Bs[8][128];
    int tid = threadIdx.x;
    int brow = blockIdx.y * 128;
    int bcol = blockIdx.x * 128;
    int lr = tid >> 1;            // 0..127
    int lc = (tid & 1) * 4;       // 0 or 4
    int tx = tid & 15;            // n quad
    int ty = tid >> 4;            // m quad
    float acc[8][8];
#pragma unroll
    for (int i = 0; i < 8; i++)
#pragma unroll
        for (int j = 0; j < 8; j++) acc[i][j] = 0.f;

    for (int k0 = 0; k0 < HID; k0 += 8) {
        float4 a = *(const float4*)&A[(size_t)(brow + lr) * HID + k0 + lc];
        float4 sc4 = *(const float4*)&g_scale[k0 + lc];
        float4 sh4 = *(const float4*)&g_shift[k0 + lc];
        As[lc + 0][lr] = fmaxf(0.f, a.x * sc4.x + sh4.x);
        As[lc + 1][lr] = fmaxf(0.f, a.y * sc4.y + sh4.y);
        As[lc + 2][lr] = fmaxf(0.f, a.z * sc4.z + sh4.z);
        As[lc + 3][lr] = fmaxf(0.f, a.w * sc4.w + sh4.w);
        float4 b = *(const float4*)&W[(size_t)(bcol + lr) * HID + k0 + lc];
        Bs[lc + 0][lr] = b.x;
        Bs[lc + 1][lr] = b.y;
        Bs[lc + 2][lr] = b.z;
        Bs[lc + 3][lr] = b.w;
        __syncthreads();
#pragma unroll
        for (int kk = 0; kk < 8; kk++) {
            float ar[8], br[8];
            *(float4*)&ar[0] = *(float4*)&As[kk][ty * 8];
            *(float4*)&ar[4] = *(float4*)&As[kk][ty * 8 + 4];
            *(float4*)&br[0] = *(float4*)&Bs[kk][tx * 8];
            *(float4*)&br[4] = *(float4*)&Bs[kk][tx * 8 + 4];
#pragma unroll
            for (int i = 0; i < 8; i++)
#pragma unroll
                for (int j = 0; j < 8; j++)
                    acc[i][j] += ar[i] * br[j];
        }
        __syncthreads();
    }
#pragma unroll
    for (int i = 0; i < 8; i++) {
        int row = brow + ty * 8 + i;
#pragma unroll
        for (int j = 0; j < 8; j++) {
            int col = bcol + tx * 8 + j;
            C[(size_t)row * HID + col] = acc[i][j] + bias[col];
        }
    }
}

// ---------------- embed: relu(bn(z0_row)) @ W_out^T + b_out, then L2 norm ----------------
__global__ void k_embed(const float* __restrict__ Wout, const float* __restrict__ bout) {
    int k = blockIdx.x;        // 4096 blocks
    int v = threadIdx.x;       // 64 threads
    __shared__ float a[HID];
    for (int m = v; m < HID; m += 64) {
        float z = g_z0[(size_t)k * HID + m];
        a[m] = fmaxf(0.f, z * g_scale[m] + g_shift[m]);
    }
    __syncthreads();
    const float* w = Wout + (size_t)v * HID;
    float s0 = 0.f, s1 = 0.f, s2 = 0.f, s3 = 0.f;
    for (int m = 0; m < HID; m += 4) {
        float4 w4 = *(const float4*)(w + m);
        s0 += a[m + 0] * w4.x;
        s1 += a[m + 1] * w4.y;
        s2 += a[m + 2] * w4.z;
        s3 += a[m + 3] * w4.w;
    }
    float y = bout[v] + ((s0 + s1) + (s2 + s3));
    __shared__ float red[64];
    red[v] = y * y;
    __syncthreads();
    for (int o = 32; o > 0; o >>= 1) {
        if (v < o) red[v] += red[v + o];
        __syncthreads();
    }
    float tot = red[0];
    float nrm = sqrtf(tot);
    float f = 1.f / (nrm + EPS_N);
    g_embed[k * VQ + v] = y * f;
    if (v == 0) g_ck[k] = 0.5f * tot * f * f;
}

// ---------------- projection: h[b,t,v] = sum_d h_in[b,d,t] * proj_w[v,d] + proj_b[v] ----------------
__global__ __launch_bounds__(256) void k_proj(const float* __restrict__ h_in,
                                              const float* __restrict__ proj_w,
                                              const float* __restrict__ proj_b) {
    __shared__ float Hs[16][64];   // [d][t]
    __shared__ float Ws[16][64];   // [d][v]
    int tid = threadIdx.x;
    int b  = blockIdx.y;
    int t0 = blockIdx.x * 64;
    int tx = tid & 15;   // v quad
    int ty = tid >> 4;   // t quad
    float acc[4][4];
#pragma unroll
    for (int i = 0; i < 4; i++)
#pragma unroll
        for (int j = 0; j < 4; j++) acc[i][j] = 0.f;

    const float* hb = h_in + (size_t)b * Dd * Tt;
    for (int d0 = 0; d0 < Dd; d0 += 16) {
        // load H slice: 16 d x 64 t
        {
            int j0 = tid * 4;                // 0..1020
            int dd = j0 >> 6;
            int tt = j0 & 63;
            float4 x = *(const float4*)&hb[(size_t)(d0 + dd) * Tt + t0 + tt];
            *(float4*)&Hs[dd][tt] = x;
        }
        // load W slice transposed: proj_w[v][d0+..]
        {
            int v = tid >> 2;
            int dq = (tid & 3) * 4;
            float4 x = *(const float4*)&proj_w[(size_t)v * Dd + d0 + dq];
            Ws[dq + 0][v] = x.x;
            Ws[dq + 1][v] = x.y;
            Ws[dq + 2][v] = x.z;
            Ws[dq + 3][v] = x.w;
        }
        __syncthreads();
#pragma unroll
        for (int dd = 0; dd < 16; dd++) {
            float4 a4 = *(float4*)&Hs[dd][ty * 4];
            float4 b4 = *(float4*)&Ws[dd][tx * 4];
            float ar[4] = {a4.x, a4.y, a4.z, a4.w};
            float br[4] = {b4.x, b4.y, b4.z, b4.w};
#pragma unroll
            for (int i = 0; i < 4; i++)
#pragma unroll
                for (int j = 0; j < 4; j++)
                    acc[i][j] += ar[i] * br[j];
        }
        __syncthreads();
    }
#pragma unroll
    for (int i = 0; i < 4; i++) {
        int row = b * Tt + t0 + ty * 4 + i;
#pragma unroll
        for (int j = 0; j < 4; j++) {
            g_hn[(size_t)row * VQ + tx * 4 + j] = acc[i][j] + proj_b[tx * 4 + j];
        }
    }
}

// ---------------- normalize hn rows ----------------
__global__ void k_hnorm() {
    int i = blockIdx.x * blockDim.x + threadIdx.x;   // BT threads
    if (i >= BT) return;
    float* r = g_hn + (size_t)i * VQ;
    float s = 0.f;
#pragma unroll
    for (int v = 0; v < VQ; v += 4) {
        float4 x = *(float4*)&r[v];
        s += x.x * x.x + x.y * x.y + x.z * x.z + x.w * x.w;
    }
    float f = 1.f / (sqrtf(s) + EPS_N);
#pragma unroll
    for (int v = 0; v < VQ; v += 4) {
        float4 x = *(float4*)&r[v];
        x.x *= f; x.y *= f; x.z *= f; x.w *= f;
        *(float4*)&r[v] = x;
    }
}

// ---------------- distance argmax: code[i] = argmax_k (hn_i . e_k - ck_k) ----------------
__global__ __launch_bounds__(256) void k_argmax() {
    __shared__ float hsT[64][64];   // [v][r]
    __shared__ float esT[64][64];   // [v][k]
    __shared__ float cks[64];
    __shared__ float rbest[64][16];
    __shared__ int   ridx[64][16];

    int tid = threadIdx.x;
    int tx = tid & 15;    // k quad
    int ty = tid >> 4;    // row quad
    int r0 = blockIdx.x * 64;

    // load 64 h rows transposed
#pragma unroll
    for (int i = 0; i < 4; i++) {
        int j = tid + i * 256;        // one float4 each
        int r = j >> 4;
        int vq = (j & 15) * 4;
        float4 x = *(const float4*)&g_hn[(size_t)(r0 + r) * VQ + vq];
        hsT[vq + 0][r] = x.x;
        hsT[vq + 1][r] = x.y;
        hsT[vq + 2][r] = x.z;
        hsT[vq + 3][r] = x.w;
    }

    float best[4];
    int   bidx[4];
#pragma unroll
    for (int i = 0; i < 4; i++) { best[i] = -3.4e38f; bidx[i] = 0; }

    for (int kt = 0; kt < KK / 64; kt++) {
        int k0 = kt * 64;
        __syncthreads();
#pragma unroll
        for (int i = 0; i < 4; i++) {
            int j = tid + i * 256;
            int r = j >> 4;
            int vq = (j & 15) * 4;
            float4 x = *(const float4*)&g_embed[(size_t)(k0 + r) * VQ + vq];
            esT[vq + 0][r] = x.x;
            esT[vq + 1][r] = x.y;
            esT[vq + 2][r] = x.z;
            esT[vq + 3][r] = x.w;
        }
        if (tid < 64) cks[tid] = g_ck[k0 + tid];
        __syncthreads();

        float acc[4][4];
#pragma unroll
        for (int i = 0; i < 4; i++)
#pragma unroll
            for (int j = 0; j < 4; j++) acc[i][j] = 0.f;

#pragma unroll 8
        for (int v = 0; v < 64; v++) {
            float4 a4 = *(float4*)&hsT[v][ty * 4];
            float4 b4 = *(float4*)&esT[v][tx * 4];
            float ar[4] = {a4.x, a4.y, a4.z, a4.w};
            float br[4] = {b4.x, b4.y, b4.z, b4.w};
#pragma unroll
            for (int i = 0; i < 4; i++)
#pragma unroll
                for (int j = 0; j < 4; j++)
                    acc[i][j] += ar[i] * br[j];
        }
#pragma unroll
        for (int i = 0; i < 4; i++) {
#pragma unroll
            for (int j = 0; j < 4; j++) {
                int kg = k0 + tx * 4 + j;
                float s = acc[i][j] - cks[tx * 4 + j];
                if (s > best[i] || (s == best[i] && kg < bidx[i])) {
                    best[i] = s; bidx[i] = kg;
                }
            }
        }
    }
    __syncthreads();
#pragma unroll
    for (int i = 0; i < 4; i++) {
        int r = ty * 4 + i;
        rbest[r][tx] = best[i];
        ridx[r][tx]  = bidx[i];
    }
    __syncthreads();
    if (tid < 64) {
        float b = rbest[tid][0];
        int   ix = ridx[tid][0];
        for (int q = 1; q < 16; q++) {
            float s = rbest[tid][q];
            int   k = ridx[tid][q];
            if (s > b || (s == b && k < ix)) { b = s; ix = k; }
        }
        g_code[r0 + tid] = ix;
    }
}

// ---------------- output: quantized = (mask? embed[code]:0) @ inv_w^T + inv_b ----------------
__global__ __launch_bounds__(256) void k_output(const int* __restrict__ attn_mask,
                                                const float* __restrict__ inv_w,
                                                const float* __restrict__ inv_b,
                                                float* __restrict__ out,
                                                int write_code, float* __restrict__ code_out) {
    __shared__ float es[32][65];
    __shared__ float ws[64][64];
    __shared__ int codes[32];
    __shared__ int msk[32];
    int tid = threadIdx.x;
    int r0 = blockIdx.x * 32;
    if (tid < 32) {
        int i = r0 + tid;
        int c = g_code[i];
        int m = attn_mask[i];
        codes[tid] = c;
        msk[tid] = m;
        if (write_code) code_out[i] = (float)((m == 1) ? c : 0);
    }
    __syncthreads();
    for (int j = tid; j < 32 * 64; j += 256) {
        int r = j >> 6;
        int v = j & 63;
        es[r][v] = (msk[r] == 1) ? g_embed[(size_t)codes[r] * VQ + v] : 0.f;
    }
    int r = tid & 31;
    int ddb = (tid >> 5) * 8;
    for (int d0 = 0; d0 < Dd; d0 += 64) {
        __syncthreads();
        for (int j = tid; j < 64 * 64; j += 256) {
            int dd = j >> 6;
            int v = j & 63;
            ws[dd][v] = inv_w[(size_t)(d0 + dd) * VQ + v];
        }
        __syncthreads();
#pragma unroll
        for (int q = 0; q < 8; q++) {
            int dd = ddb + q;
            float s = inv_b[d0 + dd];
#pragma unroll
            for (int v = 0; v < 64; v += 4) {
                float4 w4 = *(float4*)&ws[dd][v];
                s += es[r][v + 0] * w4.x + es[r][v + 1] * w4.y
                   + es[r][v + 2] * w4.z + es[r][v + 3] * w4.w;
            }
            out[(size_t)(r0 + r) * Dd + d0 + dd] = s;
        }
    }
}

// ---------------- host launcher ----------------
extern "C" void kernel_launch(void* const* d_in, const int* in_sizes, int n_in,
                              void* d_out, int out_size) {
    const float* h_in      = (const float*)d_in[0];
    const int*   attn_mask = (const int*)  d_in[1];
    const float* proj_w    = (const float*)d_in[2];
    const float* proj_b    = (const float*)d_in[3];
    const float* inv_w     = (const float*)d_in[4];
    const float* inv_b     = (const float*)d_in[5];
    const float* mlp_w_in  = (const float*)d_in[6];
    const float* mlp_b_in  = (const float*)d_in[7];
    const float* mlp_w_mid = (const float*)d_in[8];
    const float* mlp_b_mid = (const float*)d_in[9];
    const float* mlp_w_out = (const float*)d_in[10];
    const float* mlp_b_out = (const float*)d_in[11];
    const float* bn_gamma  = (const float*)d_in[12];
    const float* bn_beta   = (const float*)d_in[13];
    float* out = (float*)d_out;

    // codebook MLP
    k_layer0<<<KK * HID / 256, 256>>>(mlp_w_in, mlp_b_in);
    k_bnstats<<<HID, 256>>>(0, bn_gamma + 0 * HID, bn_beta + 0 * HID);

    dim3 ggrid(HID / 128, KK / 128);
    // layer 1: z0 -> z1
    k_gemm<<<ggrid, 256>>>(0, mlp_w_mid + 0 * (size_t)HID * HID, mlp_b_mid + 0 * HID);
    k_bnstats<<<HID, 256>>>(1, bn_gamma + 1 * HID, bn_beta + 1 * HID);
    // layer 2: z1 -> z0
    k_gemm<<<ggrid, 256>>>(1, mlp_w_mid + 1 * (size_t)HID * HID, mlp_b_mid + 1 * HID);
    k_bnstats<<<HID, 256>>>(0, bn_gamma + 2 * HID, bn_beta + 2 * HID);
    // layer 3: z0 -> z1
    k_gemm<<<ggrid, 256>>>(0, mlp_w_mid + 2 * (size_t)HID * HID, mlp_b_mid + 2 * HID);
    k_bnstats<<<HID, 256>>>(1, bn_gamma + 3 * HID, bn_beta + 3 * HID);
    // layer 4: z1 -> z0
    k_gemm<<<ggrid, 256>>>(1, mlp_w_mid + 3 * (size_t)HID * HID, mlp_b_mid + 3 * HID);
    k_bnstats<<<HID, 256>>>(0, bn_gamma + 4 * HID, bn_beta + 4 * HID);

    // embed + L2norm (reads g_z0 with bn4 scale/shift)
    k_embed<<<KK, 64>>>(mlp_w_out, mlp_b_out);

    // hidden projection + normalize
    {
        dim3 pg(Tt / 64, Bb);
        k_proj<<<pg, 256>>>(h_in, proj_w, proj_b);
    }
    k_hnorm<<<BT / 256, 256>>>();

    // nearest-code argmax
    k_argmax<<<BT / 64, 256>>>();

    // output
    const long long qelems = (long long)BT * Dd;
    int write_code = (out_size >= qelems + BT) ? 1 : 0;
    k_output<<<BT / 32, 256>>>(attn_mask, inv_w, inv_b, out, write_code, out + qelems);
}

// round 7
// speedup vs baseline: 1.0010x; 1.0010x over previous
#include <cuda_runtime.h>
#include <cuda_bf16.h>
#include <math.h>

// Problem constants
#define Bb 8
#define Tt 2048
#define Dd 768
#define VQ 64
#define L2b 12
#define HID 1024
#define KK 4096
#define NMID 4
#define BT (Bb*Tt)          // 16384
#define EPS_N 1e-6f
#define EPS_BN 1e-5f

// ---------------- device scratch (no allocs allowed) ----------------
__device__ float g_z0[KK*HID];
__device__ float g_z1[KK*HID];
__device__ float g_scale[HID];
__device__ float g_shift[HID];
__device__ float g_embed[KK*VQ];
__device__ float g_ck[KK];          // 0.5 * ||e_k||^2
__device__ float g_hn[BT*VQ];
__device__ int   g_code[BT];

// ---------------- layer 0: bits @ W_in^T + b_in -> g_z0 ----------------
__global__ void k_layer0(const float* __restrict__ w_in, const float* __restrict__ b_in) {
    int idx = blockIdx.x * blockDim.x + threadIdx.x;     // KK*HID threads
    int k = idx >> 10;
    int h = idx & 1023;
    const float* w = w_in + h * L2b;
    float s = b_in[h];
#pragma unroll
    for (int j = 0; j < L2b; j++) {
        if ((k >> (11 - j)) & 1) s += w[j];
    }
    g_z0[idx] = s;
}

// ---------------- BN stats over K=4096 rows, per column ----------------
// which==0 reads g_z0, which==1 reads g_z1
__global__ void k_bnstats(int which, const float* __restrict__ gamma, const float* __restrict__ beta) {
    const float* Z = which ? g_z1 : g_z0;
    int h = blockIdx.x;
    int t = threadIdx.x;  // 256
    double s = 0.0, s2 = 0.0;
    for (int k = t; k < KK; k += 256) {
        float v = Z[k * HID + h];
        s += (double)v;
        s2 += (double)v * (double)v;
    }
    __shared__ double ss[256], ss2[256];
    ss[t] = s; ss2[t] = s2;
    __syncthreads();
    for (int o = 128; o > 0; o >>= 1) {
        if (t < o) { ss[t] += ss[t + o]; ss2[t] += ss2[t + o]; }
        __syncthreads();
    }
    if (t == 0) {
        double m = ss[0] / (double)KK;
        double var = ss2[0] / (double)KK - m * m;
        if (var < 0.0) var = 0.0;
        float rstd = (float)(1.0 / sqrt(var + (double)EPS_BN));
        float sc = gamma[h] * rstd;
        g_scale[h] = sc;
        g_shift[h] = beta[h] - (float)m * sc;
    }
}

// ---------------- mid GEMM: C = relu(bn(A)) @ W^T + bias ----------------
// A [4096,1024], W [1024,1024] row-major (out,in). 128x128x8 tile, 8x8 microtile.
// src==0: A=g_z0, C=g_z1 ; src==1: A=g_z1, C=g_z0
__global__ __launch_bounds__(256) void k_gemm(int src, const float* __restrict__ W,
                                              const float* __restrict__ bias) {
    const float* A = src ? g_z1 : g_z0;
    float* C       = src ? g_z0 : g_z1;
    __shared__ float As[8][128];
    __shared__ float Bs[8][128];
    int tid = threadIdx.x;
    int brow = blockIdx.y * 128;
    int bcol = blockIdx.x * 128;
    int lr = tid >> 1;            // 0..127
    int lc = (tid & 1) * 4;       // 0 or 4
    int tx = tid & 15;            // n quad
    int ty = tid >> 4;            // m quad
    float acc[8][8];
#pragma unroll
    for (int i = 0; i < 8; i++)
#pragma unroll
        for (int j = 0; j < 8; j++) acc[i][j] = 0.f;

    for (int k0 = 0; k0 < HID; k0 += 8) {
        float4 a = *(const float4*)&A[(size_t)(brow + lr) * HID + k0 + lc];
        float4 sc4 = *(const float4*)&g_scale[k0 + lc];
        float4 sh4 = *(const float4*)&g_shift[k0 + lc];
        As[lc + 0][lr] = fmaxf(0.f, a.x * sc4.x + sh4.x);
        As[lc + 1][lr] = fmaxf(0.f, a.y * sc4.y + sh4.y);
        As[lc + 2][lr] = fmaxf(0.f, a.z * sc4.z + sh4.z);
        As[lc + 3][lr] = fmaxf(0.f, a.w * sc4.w + sh4.w);
        float4 b = *(const float4*)&W[(size_t)(bcol + lr) * HID + k0 + lc];
        Bs[lc + 0][lr] = b.x;
        Bs[lc + 1][lr] = b.y;
        Bs[lc + 2][lr] = b.z;
        Bs[lc + 3][lr] = b.w;
        __syncthreads();
#pragma unroll
        for (int kk = 0; kk < 8; kk++) {
            float ar[8], br[8];
            *(float4*)&ar[0] = *(float4*)&As[kk][ty * 8];
            *(float4*)&ar[4] = *(float4*)&As[kk][ty * 8 + 4];
            *(float4*)&br[0] = *(float4*)&Bs[kk][tx * 8];
            *(float4*)&br[4] = *(float4*)&Bs[kk][tx * 8 + 4];
#pragma unroll
            for (int i = 0; i < 8; i++)
#pragma unroll
                for (int j = 0; j < 8; j++)
                    acc[i][j] += ar[i] * br[j];
        }
        __syncthreads();
    }
#pragma unroll
    for (int i = 0; i < 8; i++) {
        int row = brow + ty * 8 + i;
#pragma unroll
        for (int j = 0; j < 8; j++) {
            int col = bcol + tx * 8 + j;
            C[(size_t)row * HID + col] = acc[i][j] + bias[col];
        }
    }
}

// ---------------- embed: relu(bn(z0_row)) @ W_out^T + b_out, then L2 norm ----------------
__global__ void k_embed(const float* __restrict__ Wout, const float* __restrict__ bout) {
    int k = blockIdx.x;        // 4096 blocks
    int v = threadIdx.x;       // 64 threads
    __shared__ float a[HID];
    for (int m = v; m < HID; m += 64) {
        float z = g_z0[(size_t)k * HID + m];
        a[m] = fmaxf(0.f, z * g_scale[m] + g_shift[m]);
    }
    __syncthreads();
    const float* w = Wout + (size_t)v * HID;
    float s0 = 0.f, s1 = 0.f, s2 = 0.f, s3 = 0.f;
    for (int m = 0; m < HID; m += 4) {
        float4 w4 = *(const float4*)(w + m);
        s0 += a[m + 0] * w4.x;
        s1 += a[m + 1] * w4.y;
        s2 += a[m + 2] * w4.z;
        s3 += a[m + 3] * w4.w;
    }
    float y = bout[v] + ((s0 + s1) + (s2 + s3));
    __shared__ float red[64];
    red[v] = y * y;
    __syncthreads();
    for (int o = 32; o > 0; o >>= 1) {
        if (v < o) red[v] += red[v + o];
        __syncthreads();
    }
    float tot = red[0];
    float nrm = sqrtf(tot);
    float f = 1.f / (nrm + EPS_N);
    g_embed[k * VQ + v] = y * f;
    if (v == 0) g_ck[k] = 0.5f * tot * f * f;
}

// ---------------- projection: h[b,t,v] = sum_d h_in[b,d,t] * proj_w[v,d] + proj_b[v] ----------------
__global__ __launch_bounds__(256) void k_proj(const float* __restrict__ h_in,
                                              const float* __restrict__ proj_w,
                                              const float* __restrict__ proj_b) {
    __shared__ float Hs[16][64];   // [d][t]
    __shared__ float Ws[16][64];   // [d][v]
    int tid = threadIdx.x;
    int b  = blockIdx.y;
    int t0 = blockIdx.x * 64;
    int tx = tid & 15;   // v quad
    int ty = tid >> 4;   // t quad
    float acc[4][4];
#pragma unroll
    for (int i = 0; i < 4; i++)
#pragma unroll
        for (int j = 0; j < 4; j++) acc[i][j] = 0.f;

    const float* hb = h_in + (size_t)b * Dd * Tt;
    for (int d0 = 0; d0 < Dd; d0 += 16) {
        // load H slice: 16 d x 64 t
        {
            int j0 = tid * 4;                // 0..1020
            int dd = j0 >> 6;
            int tt = j0 & 63;
            float4 x = *(const float4*)&hb[(size_t)(d0 + dd) * Tt + t0 + tt];
            *(float4*)&Hs[dd][tt] = x;
        }
        // load W slice transposed: proj_w[v][d0+..]
        {
            int v = tid >> 2;
            int dq = (tid & 3) * 4;
            float4 x = *(const float4*)&proj_w[(size_t)v * Dd + d0 + dq];
            Ws[dq + 0][v] = x.x;
            Ws[dq + 1][v] = x.y;
            Ws[dq + 2][v] = x.z;
            Ws[dq + 3][v] = x.w;
        }
        __syncthreads();
#pragma unroll
        for (int dd = 0; dd < 16; dd++) {
            float4 a4 = *(float4*)&Hs[dd][ty * 4];
            float4 b4 = *(float4*)&Ws[dd][tx * 4];
            float ar[4] = {a4.x, a4.y, a4.z, a4.w};
            float br[4] = {b4.x, b4.y, b4.z, b4.w};
#pragma unroll
            for (int i = 0; i < 4; i++)
#pragma unroll
                for (int j = 0; j < 4; j++)
                    acc[i][j] += ar[i] * br[j];
        }
        __syncthreads();
    }
#pragma unroll
    for (int i = 0; i < 4; i++) {
        int row = b * Tt + t0 + ty * 4 + i;
#pragma unroll
        for (int j = 0; j < 4; j++) {
            g_hn[(size_t)row * VQ + tx * 4 + j] = acc[i][j] + proj_b[tx * 4 + j];
        }
    }
}

// ---------------- normalize hn rows ----------------
__global__ void k_hnorm() {
    int i = blockIdx.x * blockDim.x + threadIdx.x;   // BT threads
    if (i >= BT) return;
    float* r = g_hn + (size_t)i * VQ;
    float s = 0.f;
#pragma unroll
    for (int v = 0; v < VQ; v += 4) {
        float4 x = *(float4*)&r[v];
        s += x.x * x.x + x.y * x.y + x.z * x.z + x.w * x.w;
    }
    float f = 1.f / (sqrtf(s) + EPS_N);
#pragma unroll
    for (int v = 0; v < VQ; v += 4) {
        float4 x = *(float4*)&r[v];
        x.x *= f; x.y *= f; x.z *= f; x.w *= f;
        *(float4*)&r[v] = x;
    }
}

// ---------------- distance argmax: code[i] = argmax_k (hn_i . e_k - ck_k) ----------------
__global__ __launch_bounds__(256) void k_argmax() {
    __shared__ float hsT[64][64];   // [v][r]
    __shared__ float esT[64][64];   // [v][k]
    __shared__ float cks[64];
    __shared__ float rbest[64][16];
    __shared__ int   ridx[64][16];

    int tid = threadIdx.x;
    int tx = tid & 15;    // k quad
    int ty = tid >> 4;    // row quad
    int r0 = blockIdx.x * 64;

    // load 64 h rows transposed
#pragma unroll
    for (int i = 0; i < 4; i++) {
        int j = tid + i * 256;        // one float4 each
        int r = j >> 4;
        int vq = (j & 15) * 4;
        float4 x = *(const float4*)&g_hn[(size_t)(r0 + r) * VQ + vq];
        hsT[vq + 0][r] = x.x;
        hsT[vq + 1][r] = x.y;
        hsT[vq + 2][r] = x.z;
        hsT[vq + 3][r] = x.w;
    }

    float best[4];
    int   bidx[4];
#pragma unroll
    for (int i = 0; i < 4; i++) { best[i] = -3.4e38f; bidx[i] = 0; }

    for (int kt = 0; kt < KK / 64; kt++) {
        int k0 = kt * 64;
        __syncthreads();
#pragma unroll
        for (int i = 0; i < 4; i++) {
            int j = tid + i * 256;
            int r = j >> 4;
            int vq = (j & 15) * 4;
            float4 x = *(const float4*)&g_embed[(size_t)(k0 + r) * VQ + vq];
            esT[vq + 0][r] = x.x;
            esT[vq + 1][r] = x.y;
            esT[vq + 2][r] = x.z;
            esT[vq + 3][r] = x.w;
        }
        if (tid < 64) cks[tid] = g_ck[k0 + tid];
        __syncthreads();

        float acc[4][4];
#pragma unroll
        for (int i = 0; i < 4; i++)
#pragma unroll
            for (int j = 0; j < 4; j++) acc[i][j] = 0.f;

#pragma unroll 8
        for (int v = 0; v < 64; v++) {
            float4 a4 = *(float4*)&hsT[v][ty * 4];
            float4 b4 = *(float4*)&esT[v][tx * 4];
            float ar[4] = {a4.x, a4.y, a4.z, a4.w};
            float br[4] = {b4.x, b4.y, b4.z, b4.w};
#pragma unroll
            for (int i = 0; i < 4; i++)
#pragma unroll
                for (int j = 0; j < 4; j++)
                    acc[i][j] += ar[i] * br[j];
        }
#pragma unroll
        for (int i = 0; i < 4; i++) {
#pragma unroll
            for (int j = 0; j < 4; j++) {
                int kg = k0 + tx * 4 + j;
                float s = acc[i][j] - cks[tx * 4 + j];
                if (s > best[i] || (s == best[i] && kg < bidx[i])) {
                    best[i] = s; bidx[i] = kg;
                }
            }
        }
    }
    __syncthreads();
#pragma unroll
    for (int i = 0; i < 4; i++) {
        int r = ty * 4 + i;
        rbest[r][tx] = best[i];
        ridx[r][tx]  = bidx[i];
    }
    __syncthreads();
    if (tid < 64) {
        float b = rbest[tid][0];
        int   ix = ridx[tid][0];
        for (int q = 1; q < 16; q++) {
            float s = rbest[tid][q];
            int   k = ridx[tid][q];
            if (s > b || (s == b && k < ix)) { b = s; ix = k; }
        }
        g_code[r0 + tid] = ix;
    }
}

// ---------------- output: quantized = (mask? embed[code]:0) @ inv_w^T + inv_b ----------------
__global__ __launch_bounds__(256) void k_output(const int* __restrict__ attn_mask,
                                                const float* __restrict__ inv_w,
                                                const float* __restrict__ inv_b,
                                                float* __restrict__ out,
                                                int write_code, float* __restrict__ code_out) {
    __shared__ float es[32][65];
    __shared__ float ws[64][64];
    __shared__ int codes[32];
    __shared__ int msk[32];
    int tid = threadIdx.x;
    int r0 = blockIdx.x * 32;
    if (tid < 32) {
        int i = r0 + tid;
        int c = g_code[i];
        int m = attn_mask[i];
        codes[tid] = c;
        msk[tid] = m;
        if (write_code) code_out[i] = (float)((m == 1) ? c : 0);
    }
    __syncthreads();
    for (int j = tid; j < 32 * 64; j += 256) {
        int r = j >> 6;
        int v = j & 63;
        es[r][v] = (msk[r] == 1) ? g_embed[(size_t)codes[r] * VQ + v] : 0.f;
    }
    int r = tid & 31;
    int ddb = (tid >> 5) * 8;
    for (int d0 = 0; d0 < Dd; d0 += 64) {
        __syncthreads();
        for (int j = tid; j < 64 * 64; j += 256) {
            int dd = j >> 6;
            int v = j & 63;
            ws[dd][v] = inv_w[(size_t)(d0 + dd) * VQ + v];
        }
        __syncthreads();
#pragma unroll
        for (int q = 0; q < 8; q++) {
            int dd = ddb + q;
            float s = inv_b[d0 + dd];
#pragma unroll
            for (int v = 0; v < 64; v += 4) {
                float4 w4 = *(float4*)&ws[dd][v];
                s += es[r][v + 0] * w4.x + es[r][v + 1] * w4.y
                   + es[r][v + 2] * w4.z + es[r][v + 3] * w4.w;
            }
            out[(size_t)(r0 + r) * Dd + d0 + dd] = s;
        }
    }
}

// ---------------- host launcher ----------------
extern "C" void kernel_launch(void* const* d_in, const int* in_sizes, int n_in,
                              void* d_out, int out_size) {
    const float* h_in      = (const float*)d_in[0];
    const int*   attn_mask = (const int*)  d_in[1];
    const float* proj_w    = (const float*)d_in[2];
    const float* proj_b    = (const float*)d_in[3];
    const float* inv_w     = (const float*)d_in[4];
    const float* inv_b     = (const float*)d_in[5];
    const float* mlp_w_in  = (const float*)d_in[6];
    const float* mlp_b_in  = (const float*)d_in[7];
    const float* mlp_w_mid = (const float*)d_in[8];
    const float* mlp_b_mid = (const float*)d_in[9];
    const float* mlp_w_out = (const float*)d_in[10];
    const float* mlp_b_out = (const float*)d_in[11];
    const float* bn_gamma  = (const float*)d_in[12];
    const float* bn_beta   = (const float*)d_in[13];
    float* out = (float*)d_out;

    // codebook MLP
    k_layer0<<<KK * HID / 256, 256>>>(mlp_w_in, mlp_b_in);
    k_bnstats<<<HID, 256>>>(0, bn_gamma + 0 * HID, bn_beta + 0 * HID);

    dim3 ggrid(HID / 128, KK / 128);
    // layer 1: z0 -> z1
    k_gemm<<<ggrid, 256>>>(0, mlp_w_mid + 0 * (size_t)HID * HID, mlp_b_mid + 0 * HID);
    k_bnstats<<<HID, 256>>>(1, bn_gamma + 1 * HID, bn_beta + 1 * HID);
    // layer 2: z1 -> z0
    k_gemm<<<ggrid, 256>>>(1, mlp_w_mid + 1 * (size_t)HID * HID, mlp_b_mid + 1 * HID);
    k_bnstats<<<HID, 256>>>(0, bn_gamma + 2 * HID, bn_beta + 2 * HID);
    // layer 3: z0 -> z1
    k_gemm<<<ggrid, 256>>>(0, mlp_w_mid + 2 * (size_t)HID * HID, mlp_b_mid + 2 * HID);
    k_bnstats<<<HID, 256>>>(1, bn_gamma + 3 * HID, bn_beta + 3 * HID);
    // layer 4: z1 -> z0
    k_gemm<<<ggrid, 256>>>(1, mlp_w_mid + 3 * (size_t)HID * HID, mlp_b_mid + 3 * HID);
    k_bnstats<<<HID, 256>>>(0, bn_gamma + 4 * HID, bn_beta + 4 * HID);

    // embed + L2norm (reads g_z0 with bn4 scale/shift)
    k_embed<<<KK, 64>>>(mlp_w_out, mlp_b_out);

    // hidden projection + normalize
    {
        dim3 pg(Tt / 64, Bb);
        k_proj<<<pg, 256>>>(h_in, proj_w, proj_b);
    }
    k_hnorm<<<BT / 256, 256>>>();

    // nearest-code argmax
    k_argmax<<<BT / 64, 256>>>();

    // output
    const long long qelems = (long long)BT * Dd;
    int write_code = (out_size >= qelems + BT) ? 1 : 0;
    k_output<<<BT / 32, 256>>>(attn_mask, inv_w, inv_b, out, write_code, out + qelems);
}

// round 8
// speedup vs baseline: 1.2215x; 1.2203x over previous
#include <cuda_runtime.h>
#include <math.h>

#define Bb 8
#define Tt 2048
#define Dd 768
#define VQ 64
#define L2b 12
#define HID 1024
#define KK 4096
#define BT (Bb*Tt)
#define EPS_N 1e-6f
#define EPS_BN 1e-5f

__device__ float g_z0[KK*HID];
__device__ float g_z1[KK*HID];
__device__ float g_scale[HID];
__device__ float g_shift[HID];
__device__ float g_embed[KK*VQ];
__device__ float g_ck[KK];
__device__ float g_hn[BT*VQ];
__device__ int   g_code[BT];
__device__ float g_psum[4*32*HID];
__device__ float g_psq[4*32*HID];

// ---------------- layer 0 ----------------
__global__ void k_layer0(const float* __restrict__ w_in, const float* __restrict__ b_in) {
    int idx = blockIdx.x * blockDim.x + threadIdx.x;
    int k = idx >> 10, h = idx & 1023;
    const float* w = w_in + h * L2b;
    float s = b_in[h];
#pragma unroll
    for (int j = 0; j < L2b; j++)
        if ((k >> (11 - j)) & 1) s += w[j];
    g_z0[idx] = s;
}

// ---------------- BN0 closed form (exact over full enumeration) ----------------
__global__ void k_bn0(const float* __restrict__ w_in, const float* __restrict__ b_in,
                      const float* __restrict__ gamma, const float* __restrict__ beta) {
    int h = blockIdx.x * blockDim.x + threadIdx.x;
    if (h >= HID) return;
    float s = 0.f, q = 0.f;
#pragma unroll
    for (int j = 0; j < L2b; j++) { float w = w_in[h * L2b + j]; s += w; q += w * w; }
    float m = b_in[h] + 0.5f * s;
    float rstd = (float)(1.0 / sqrt(0.25 * (double)q + (double)EPS_BN));
    float sc = gamma[h] * rstd;
    g_scale[h] = sc;
    g_shift[h] = beta[h] - m * sc;
}

// ---------------- BN finalize from GEMM partials ----------------
__global__ void k_bnfin(int layer, const float* __restrict__ gamma, const float* __restrict__ beta) {
    int h = blockIdx.x * blockDim.x + threadIdx.x;
    if (h >= HID) return;
    double s = 0.0, q = 0.0;
#pragma unroll 8
    for (int p = 0; p < 32; p++) {
        s += (double)g_psum[(layer * 32 + p) * HID + h];
        q += (double)g_psq[(layer * 32 + p) * HID + h];
    }
    double m = s / 4096.0;
    double var = q / 4096.0 - m * m;
    if (var < 0.0) var = 0.0;
    float rstd = (float)(1.0 / sqrt(var + (double)EPS_BN));
    float sc = gamma[h] * rstd;
    g_scale[h] = sc;
    g_shift[h] = beta[h] - (float)m * sc;
}

#define BN8(BUF) \
    As[BUF][lk+0][lr]=fmaxf(0.f,fmaf(a0.x,s0.x,h0.x)); \
    As[BUF][lk+1][lr]=fmaxf(0.f,fmaf(a0.y,s0.y,h0.y)); \
    As[BUF][lk+2][lr]=fmaxf(0.f,fmaf(a0.z,s0.z,h0.z)); \
    As[BUF][lk+3][lr]=fmaxf(0.f,fmaf(a0.w,s0.w,h0.w)); \
    As[BUF][lk+4][lr]=fmaxf(0.f,fmaf(a1.x,s1.x,h1.x)); \
    As[BUF][lk+5][lr]=fmaxf(0.f,fmaf(a1.y,s1.y,h1.y)); \
    As[BUF][lk+6][lr]=fmaxf(0.f,fmaf(a1.z,s1.z,h1.z)); \
    As[BUF][lk+7][lr]=fmaxf(0.f,fmaf(a1.w,s1.w,h1.w)); \
    Bs[BUF][lk+0][lr]=b0.x; Bs[BUF][lk+1][lr]=b0.y; \
    Bs[BUF][lk+2][lr]=b0.z; Bs[BUF][lk+3][lr]=b0.w; \
    Bs[BUF][lk+4][lr]=b1.x; Bs[BUF][lk+5][lr]=b1.y; \
    Bs[BUF][lk+6][lr]=b1.z; Bs[BUF][lk+7][lr]=b1.w;

// ---------------- mid GEMM: C = relu(bn(A)) @ W^T + bias, fused BN-stat partials ----------------
__global__ __launch_bounds__(256, 2) void k_gemm(int src, int layer,
                                                 const float* __restrict__ W,
                                                 const float* __restrict__ bias) {
    const float* __restrict__ A = src ? g_z1 : g_z0;
    float* __restrict__ C       = src ? g_z0 : g_z1;
    __shared__ float As[2][16][128];
    __shared__ float Bs[2][16][128];
    const int tid = threadIdx.x;
    const int brow = blockIdx.y * 128, bcol = blockIdx.x * 128;
    const int lr = tid >> 1, lk = (tid & 1) * 8;
    const int tx = tid & 15, ty = tid >> 4;
    const float* Ap = A + (size_t)(brow + lr) * HID + lk;
    const float* Wp = W + (size_t)(bcol + lr) * HID + lk;
    float4 a0, a1, b0, b1;
    a0 = *(const float4*)Ap;       a1 = *(const float4*)(Ap + 4);
    b0 = *(const float4*)Wp;       b1 = *(const float4*)(Wp + 4);
    {
        float4 s0 = *(const float4*)&g_scale[lk], s1 = *(const float4*)&g_scale[lk + 4];
        float4 h0 = *(const float4*)&g_shift[lk], h1 = *(const float4*)&g_shift[lk + 4];
        BN8(0)
    }
    __syncthreads();
    float acc[8][8] = {};
    for (int t = 0; t < 64; t++) {
        int cur = t & 1, nx = cur ^ 1;
        if (t < 63) {
            int kn = (t + 1) * 16;
            a0 = *(const float4*)(Ap + kn); a1 = *(const float4*)(Ap + kn + 4);
            b0 = *(const float4*)(Wp + kn); b1 = *(const float4*)(Wp + kn + 4);
        }
#pragma unroll
        for (int kk = 0; kk < 16; kk++) {
            float ar[8], br[8];
            *(float4*)&ar[0] = *(const float4*)&As[cur][kk][ty * 4];
            *(float4*)&ar[4] = *(const float4*)&As[cur][kk][64 + ty * 4];
            *(float4*)&br[0] = *(const float4*)&Bs[cur][kk][tx * 4];
            *(float4*)&br[4] = *(const float4*)&Bs[cur][kk][64 + tx * 4];
#pragma unroll
            for (int i = 0; i < 8; i++)
#pragma unroll
                for (int j = 0; j < 8; j++)
                    acc[i][j] = fmaf(ar[i], br[j], acc[i][j]);
        }
        if (t < 63) {
            int kn = (t + 1) * 16 + lk;
            float4 s0 = *(const float4*)&g_scale[kn], s1 = *(const float4*)&g_scale[kn + 4];
            float4 h0 = *(const float4*)&g_shift[kn], h1 = *(const float4*)&g_shift[kn + 4];
            if (nx) { BN8(1) } else { BN8(0) }
        }
        __syncthreads();
    }
    // epilogue: bias + store + column partial stats
    float bj[8];
    *(float4*)&bj[0] = *(const float4*)&bias[bcol + tx * 4];
    *(float4*)&bj[4] = *(const float4*)&bias[bcol + 64 + tx * 4];
    float cs[8] = {}, cq[8] = {};
#pragma unroll
    for (int i = 0; i < 8; i++) {
        int row = brow + ((i < 4) ? (ty * 4 + i) : (64 + ty * 4 + i - 4));
        float v[8];
#pragma unroll
        for (int j = 0; j < 8; j++) {
            v[j] = acc[i][j] + bj[j];
            cs[j] += v[j];
            cq[j] += v[j] * v[j];
        }
        *(float4*)&C[(size_t)row * HID + bcol + tx * 4]      = *(float4*)&v[0];
        *(float4*)&C[(size_t)row * HID + bcol + 64 + tx * 4] = *(float4*)&v[4];
    }
    float* reds = &As[0][0][0];
    float* redq = reds + 2048;
#pragma unroll
    for (int j = 0; j < 8; j++) {
        int c = (j < 4) ? (tx * 4 + j) : (64 + tx * 4 + j - 4);
        reds[ty * 128 + c] = cs[j];
        redq[ty * 128 + c] = cq[j];
    }
    __syncthreads();
    if (tid < 128) {
        float s = 0.f, q = 0.f;
#pragma unroll
        for (int yy = 0; yy < 16; yy++) { s += reds[yy * 128 + tid]; q += redq[yy * 128 + tid]; }
        g_psum[(layer * 32 + blockIdx.y) * HID + bcol + tid] = s;
        g_psq [(layer * 32 + blockIdx.y) * HID + bcol + tid] = q;
    }
}

// ---------------- embed: relu(bn(z0_row)) @ W_out^T + b_out, L2 norm ----------------
__global__ void k_embed(const float* __restrict__ Wout, const float* __restrict__ bout) {
    int k = blockIdx.x;
    int v = threadIdx.x;
    __shared__ float a[HID];
    for (int m = v; m < HID; m += 64) {
        float z = g_z0[(size_t)k * HID + m];
        a[m] = fmaxf(0.f, fmaf(z, g_scale[m], g_shift[m]));
    }
    __syncthreads();
    const float* w = Wout + (size_t)v * HID;
    float s0 = 0.f, s1 = 0.f, s2 = 0.f, s3 = 0.f;
    for (int m = 0; m < HID; m += 4) {
        float4 w4 = *(const float4*)(w + m);
        s0 = fmaf(a[m + 0], w4.x, s0);
        s1 = fmaf(a[m + 1], w4.y, s1);
        s2 = fmaf(a[m + 2], w4.z, s2);
        s3 = fmaf(a[m + 3], w4.w, s3);
    }
    float y = bout[v] + ((s0 + s1) + (s2 + s3));
    __shared__ float red[64];
    red[v] = y * y;
    __syncthreads();
    for (int o = 32; o > 0; o >>= 1) {
        if (v < o) red[v] += red[v + o];
        __syncthreads();
    }
    float tot = red[0];
    float f = 1.f / (sqrtf(tot) + EPS_N);
    g_embed[k * VQ + v] = y * f;
    if (v == 0) g_ck[k] = 0.5f * tot * f * f;
}

// ---------------- projection + fused row L2 norm ----------------
__global__ __launch_bounds__(256) void k_proj(const float* __restrict__ h_in,
                                              const float* __restrict__ proj_w,
                                              const float* __restrict__ proj_b) {
    __shared__ float Hs[16][64];
    __shared__ float Ws[16][64];
    __shared__ float red[64][16];
    __shared__ float fac[64];
    int tid = threadIdx.x;
    int b = blockIdx.y;
    int t0 = blockIdx.x * 64;
    int tx = tid & 15, ty = tid >> 4;
    float acc[4][4] = {};
    const float* hb = h_in + (size_t)b * Dd * Tt;
    for (int d0 = 0; d0 < Dd; d0 += 16) {
        {
            int j0 = tid * 4;
            int dd = j0 >> 6, tt = j0 & 63;
            *(float4*)&Hs[dd][tt] = *(const float4*)&hb[(size_t)(d0 + dd) * Tt + t0 + tt];
        }
        {
            int v = tid >> 2, dq = (tid & 3) * 4;
            float4 x = *(const float4*)&proj_w[(size_t)v * Dd + d0 + dq];
            Ws[dq + 0][v] = x.x; Ws[dq + 1][v] = x.y; Ws[dq + 2][v] = x.z; Ws[dq + 3][v] = x.w;
        }
        __syncthreads();
#pragma unroll
        for (int dd = 0; dd < 16; dd++) {
            float ar[4], br[4];
            *(float4*)&ar[0] = *(const float4*)&Hs[dd][ty * 4];
            *(float4*)&br[0] = *(const float4*)&Ws[dd][tx * 4];
#pragma unroll
            for (int i = 0; i < 4; i++)
#pragma unroll
                for (int j = 0; j < 4; j++)
                    acc[i][j] = fmaf(ar[i], br[j], acc[i][j]);
        }
        __syncthreads();
    }
    float bj[4];
    *(float4*)&bj[0] = *(const float4*)&proj_b[tx * 4];
#pragma unroll
    for (int i = 0; i < 4; i++) {
        float p = 0.f;
#pragma unroll
        for (int j = 0; j < 4; j++) {
            float v = acc[i][j] + bj[j];
            acc[i][j] = v;
            p = fmaf(v, v, p);
        }
        red[ty * 4 + i][tx] = p;
    }
    __syncthreads();
    if (tid < 64) {
        float tot = 0.f;
#pragma unroll
        for (int q = 0; q < 16; q++) tot += red[tid][q];
        fac[tid] = 1.f / (sqrtf(tot) + EPS_N);
    }
    __syncthreads();
#pragma unroll
    for (int i = 0; i < 4; i++) {
        float f = fac[ty * 4 + i];
        float v[4];
#pragma unroll
        for (int j = 0; j < 4; j++) v[j] = acc[i][j] * f;
        size_t row = (size_t)b * Tt + t0 + ty * 4 + i;
        *(float4*)&g_hn[row * VQ + tx * 4] = *(float4*)&v[0];
    }
}

// ---------------- argmax: 64 rows x 128 codes/tile, 8x8 microtile ----------------
__global__ __launch_bounds__(128, 4) void k_argmax() {
    __shared__ float hsT[64][64];    // 16KB
    __shared__ float esT[64][128];   // 32KB
    const int tid = threadIdx.x, r0 = blockIdx.x * 64;
    const int tx = tid & 15, ty = tid >> 4;
#pragma unroll
    for (int i = 0; i < 8; i++) {
        int f = tid + i * 128;
        int r = f >> 4, vq = (f & 15) * 4;
        float4 x = *(const float4*)&g_hn[(size_t)(r0 + r) * VQ + vq];
        hsT[vq + 0][r] = x.x; hsT[vq + 1][r] = x.y;
        hsT[vq + 2][r] = x.z; hsT[vq + 3][r] = x.w;
    }
    float best[8]; int bidx[8];
#pragma unroll
    for (int i = 0; i < 8; i++) { best[i] = -3.4e38f; bidx[i] = 0; }

    for (int kt = 0; kt < 32; kt++) {
        int kb = kt * 128;
        __syncthreads();
#pragma unroll
        for (int i = 0; i < 16; i++) {
            int f = tid + i * 128;
            int code = f >> 4, vq = (f & 15) * 4;
            float4 x = *(const float4*)&g_embed[(size_t)(kb + code) * VQ + vq];
            esT[vq + 0][code] = x.x; esT[vq + 1][code] = x.y;
            esT[vq + 2][code] = x.z; esT[vq + 3][code] = x.w;
        }
        __syncthreads();
        float acc[8][8] = {};
#pragma unroll 4
        for (int v = 0; v < 64; v++) {
            float ar[8], br[8];
            *(float4*)&ar[0] = *(const float4*)&hsT[v][ty * 4];
            *(float4*)&ar[4] = *(const float4*)&hsT[v][32 + ty * 4];
            *(float4*)&br[0] = *(const float4*)&esT[v][tx * 4];
            *(float4*)&br[4] = *(const float4*)&esT[v][64 + tx * 4];
#pragma unroll
            for (int i = 0; i < 8; i++)
#pragma unroll
                for (int j = 0; j < 8; j++)
                    acc[i][j] = fmaf(ar[i], br[j], acc[i][j]);
        }
#pragma unroll
        for (int j = 0; j < 8; j++) {
            int kg = kb + ((j < 4) ? (tx * 4 + j) : (64 + tx * 4 + j - 4));
            float ck = g_ck[kg];
#pragma unroll
            for (int i = 0; i < 8; i++) {
                float s = acc[i][j] - ck;
                if (s > best[i]) { best[i] = s; bidx[i] = kg; }
            }
        }
    }
    __syncthreads();
    float* rb = &esT[0][0];
    int* ri = (int*)(rb + 1024);
#pragma unroll
    for (int i = 0; i < 8; i++) {
        int r = (i < 4) ? (ty * 4 + i) : (32 + ty * 4 + i - 4);
        rb[r * 16 + tx] = best[i];
        ri[r * 16 + tx] = bidx[i];
    }
    __syncthreads();
    if (tid < 64) {
        float b = rb[tid * 16]; int ix = ri[tid * 16];
#pragma unroll
        for (int q = 1; q < 16; q++) {
            float s = rb[tid * 16 + q];
            int k2 = ri[tid * 16 + q];
            if (s > b || (s == b && k2 < ix)) { b = s; ix = k2; }
        }
        g_code[r0 + tid] = ix;
    }
}

// ---------------- output: (mask? embed[code]:0) @ inv_w^T + inv_b ----------------
__global__ __launch_bounds__(256) void k_output(const int* __restrict__ attn_mask,
                                                const float* __restrict__ inv_w,
                                                const float* __restrict__ inv_b,
                                                float* __restrict__ out,
                                                int write_code, float* __restrict__ code_out) {
    __shared__ float es[32][65];
    __shared__ float ws[64][64];
    __shared__ int codes[32];
    __shared__ int msk[32];
    int tid = threadIdx.x;
    int r0 = blockIdx.x * 32;
    if (tid < 32) {
        int i = r0 + tid;
        int c = g_code[i];
        int m = attn_mask[i];
        codes[tid] = c;
        msk[tid] = m;
        if (write_code) code_out[i] = (float)((m == 1) ? c : 0);
    }
    __syncthreads();
    for (int j = tid; j < 32 * 64; j += 256) {
        int r = j >> 6, v = j & 63;
        es[r][v] = (msk[r] == 1) ? g_embed[(size_t)codes[r] * VQ + v] : 0.f;
    }
    int r = tid & 31;
    int ddb = (tid >> 5) * 8;
    for (int d0 = 0; d0 < Dd; d0 += 64) {
        __syncthreads();
        for (int j = tid; j < 64 * 64; j += 256) {
            int dd = j >> 6, v = j & 63;
            ws[dd][v] = inv_w[(size_t)(d0 + dd) * VQ + v];
        }
        __syncthreads();
#pragma unroll
        for (int q = 0; q < 8; q++) {
            int dd = ddb + q;
            float s = inv_b[d0 + dd];
#pragma unroll
            for (int v = 0; v < 64; v += 4) {
                float4 w4 = *(float4*)&ws[dd][v];
                s = fmaf(es[r][v + 0], w4.x, s);
                s = fmaf(es[r][v + 1], w4.y, s);
                s = fmaf(es[r][v + 2], w4.z, s);
                s = fmaf(es[r][v + 3], w4.w, s);
            }
            out[(size_t)(r0 + r) * Dd + d0 + dd] = s;
        }
    }
}

// ---------------- host launcher ----------------
extern "C" void kernel_launch(void* const* d_in, const int* in_sizes, int n_in,
                              void* d_out, int out_size) {
    const float* h_in      = (const float*)d_in[0];
    const int*   attn_mask = (const int*)  d_in[1];
    const float* proj_w    = (const float*)d_in[2];
    const float* proj_b    = (const float*)d_in[3];
    const float* inv_w     = (const float*)d_in[4];
    const float* inv_b     = (const float*)d_in[5];
    const float* mlp_w_in  = (const float*)d_in[6];
    const float* mlp_b_in  = (const float*)d_in[7];
    const float* mlp_w_mid = (const float*)d_in[8];
    const float* mlp_b_mid = (const float*)d_in[9];
    const float* mlp_w_out = (const float*)d_in[10];
    const float* mlp_b_out = (const float*)d_in[11];
    const float* bn_gamma  = (const float*)d_in[12];
    const float* bn_beta   = (const float*)d_in[13];
    float* out = (float*)d_out;

    k_layer0<<<KK * HID / 256, 256>>>(mlp_w_in, mlp_b_in);
    k_bn0<<<HID / 256, 256>>>(mlp_w_in, mlp_b_in, bn_gamma, bn_beta);

    dim3 gg(HID / 128, KK / 128);
    for (int L = 0; L < 4; L++) {
        k_gemm<<<gg, 256>>>(L & 1, L, mlp_w_mid + (size_t)L * HID * HID, mlp_b_mid + L * HID);
        k_bnfin<<<HID / 256, 256>>>(L, bn_gamma + (L + 1) * HID, bn_beta + (L + 1) * HID);
    }

    k_embed<<<KK, 64>>>(mlp_w_out, mlp_b_out);

    dim3 pg(Tt / 64, Bb);
    k_proj<<<pg, 256>>>(h_in, proj_w, proj_b);

    k_argmax<<<BT / 64, 128>>>();

    const long long qelems = (long long)BT * Dd;
    int write_code = (out_size >= qelems + BT) ? 1 : 0;
    k_output<<<BT / 32, 256>>>(attn_mask, inv_w, inv_b, out, write_code, out + qelems);
}